// round 16
// baseline (speedup 1.0000x reference)
#include <cuda_runtime.h>

#define B_ROWS   8192
#define NBINS    125
#define M_CAND   4096
#define NTOT     (NBINS * M_CAND)
#define NTHREADS 128
#define NWARPS   4
#define EARTH_R  3958.8f
#define DEG2RAD  0.017453292519943295f
#define LOG2E    1.4426950408889634f
#define K0_CONST (-4.0f * EARTH_R * LOG2E)   /* chord-space logit slope, log2 units */
#define DELTA_C  (33.0f / (4.0f * EARTH_R * LOG2E))  /* skip if exponent < -33 */

// Static scratch (no allocations allowed). SoA: 12 B per candidate.
__device__ float4 g_xyA[NTOT / 2];   // (x0,y0,x1,y1) pairs
__device__ float4 g_zA [NTOT / 4];   // (z0,z1,z2,z3) quads
__device__ float4 g_rowv[B_ROWS];    // row unit vectors
__device__ int2   g_meta[B_ROWS];    // (base index, count) per row
__device__ float  g_sum_soft;
__device__ float  g_sum_valid;
__device__ int    g_ticket;

// ---------------------------------------------------------------------------
// Kernel 1 (merged prep): candidates -> SoA unit vectors; rows -> unit vector
// + (base, count) meta; reset accumulators.
// ---------------------------------------------------------------------------
__global__ __launch_bounds__(256)
void prep_kernel(const float4* __restrict__ bin_coords4,
                 const float* __restrict__ preds,
                 const long long* __restrict__ x_vals,
                 const long long* __restrict__ bin_counts) {
    int i = blockIdx.x * 256 + threadIdx.x;
    if (i == 0) { g_ticket = 0; g_sum_soft = 0.0f; g_sum_valid = 0.0f; }
    if (i < NTOT / 4) {
        float4 c01 = __ldg(&bin_coords4[2 * i]);      // (lon0,lat0,lon1,lat1)
        float4 c23 = __ldg(&bin_coords4[2 * i + 1]);  // (lon2,lat2,lon3,lat3)
        float sla0, cla0, slo0, clo0, sla1, cla1, slo1, clo1;
        float sla2, cla2, slo2, clo2, sla3, cla3, slo3, clo3;
        __sincosf(c01.y * DEG2RAD, &sla0, &cla0);
        __sincosf(c01.x * DEG2RAD, &slo0, &clo0);
        __sincosf(c01.w * DEG2RAD, &sla1, &cla1);
        __sincosf(c01.z * DEG2RAD, &slo1, &clo1);
        __sincosf(c23.y * DEG2RAD, &sla2, &cla2);
        __sincosf(c23.x * DEG2RAD, &slo2, &clo2);
        __sincosf(c23.w * DEG2RAD, &sla3, &cla3);
        __sincosf(c23.z * DEG2RAD, &slo3, &clo3);
        g_xyA[2 * i]     = make_float4(cla0 * clo0, cla0 * slo0, cla1 * clo1, cla1 * slo1);
        g_xyA[2 * i + 1] = make_float4(cla2 * clo2, cla2 * slo2, cla3 * clo3, cla3 * slo3);
        g_zA[i]          = make_float4(sla0, sla1, sla2, sla3);
    } else if (i < NTOT / 4 + B_ROWS) {
        int b = i - NTOT / 4;
        long long bin_id = x_vals[b * 3 + 0] * 25 + x_vals[b * 3 + 1] * 5 + x_vals[b * 3 + 2];
        if (bin_id < 0) bin_id = 0;
        if (bin_id >= NBINS) bin_id = NBINS - 1;
        int count = (int)bin_counts[bin_id];
        if (count < 0) count = 0;
        if (count > M_CAND) count = M_CAND;
        float lon = preds[b * 2 + 0] * DEG2RAD;
        float lat = preds[b * 2 + 1] * DEG2RAD;
        float slat, clat, slon, clon;
        sincosf(lat, &slat, &clat);           // libm accuracy once per row
        sincosf(lon, &slon, &clon);
        g_rowv[b] = make_float4(clat * clon, clat * slon, slat, 0.0f);
        g_meta[b] = make_int2((int)bin_id * M_CAND, count);
    }
}

// ---------------------------------------------------------------------------
// Kernel 2: pass1 branchless s2-min (cached in smem, zero MUFU); pass2 reads
// smem as float4 with __any_sync-branched rare body (sqrt+exp only in the
// ~6-mile window around the exact min). Fused atomic tail reduction.
// ---------------------------------------------------------------------------
__global__ __launch_bounds__(NTHREADS)
void softbin_main_kernel(float* __restrict__ out) {
    __shared__ __align__(16) float sh_s2[M_CAND];
    __shared__ float sh_red[NWARPS];

    const int b    = blockIdx.x;
    const int tid  = threadIdx.x;
    const int warp = tid >> 5;
    const int lane = tid & 31;

    const int2  mt  = g_meta[b];
    const int base  = mt.x;                   // multiple of 4096
    const int count = mt.y;
    const float4 rv = g_rowv[b];              // broadcast LDG.128
    const float px = rv.x, py = rv.y, pz = rv.z;

    const float2* __restrict__ cxy = ((const float2*)g_xyA) + base;
    const float*  __restrict__ cz  = ((const float*)g_zA)  + base;

    // ---- pass 1: branchless min of squared chord; cache s2 in smem ----
    float mn0 = 1.0e30f, mn1 = 1.0e30f;
    int j = tid;
    for (; j + NTHREADS < count; j += 2 * NTHREADS) {
        float2 a0 = __ldg(&cxy[j]);
        float  z0 = __ldg(&cz[j]);
        float2 a1 = __ldg(&cxy[j + NTHREADS]);
        float  z1 = __ldg(&cz[j + NTHREADS]);
        float dx0 = px - a0.x, dy0 = py - a0.y, dz0 = pz - z0;
        float s20 = fmaf(dx0, dx0, fmaf(dy0, dy0, dz0 * dz0));
        float dx1 = px - a1.x, dy1 = py - a1.y, dz1 = pz - z1;
        float s21 = fmaf(dx1, dx1, fmaf(dy1, dy1, dz1 * dz1));
        sh_s2[j] = s20;
        sh_s2[j + NTHREADS] = s21;
        mn0 = fminf(mn0, s20);
        mn1 = fminf(mn1, s21);
    }
    if (j < count) {
        float2 a0 = __ldg(&cxy[j]);
        float  z0 = __ldg(&cz[j]);
        float dx0 = px - a0.x, dy0 = py - a0.y, dz0 = pz - z0;
        float s20 = fmaf(dx0, dx0, fmaf(dy0, dy0, dz0 * dz0));
        sh_s2[j] = s20;
        mn0 = fminf(mn0, s20);
    }
    mn0 = fminf(mn0, mn1);

    // pad tail so pass2 can run uniform float4 iterations
    const int n4   = (count + 3) >> 2;                  // float4 groups
    const int n4u  = (n4 + NTHREADS - 1) & ~(NTHREADS - 1);  // uniform bound
    const int padE = min(n4u * 4, M_CAND);
    for (int p = count + tid; p < padE; p += NTHREADS) sh_s2[p] = 1.0e30f;

    #pragma unroll
    for (int off = 16; off > 0; off >>= 1)
        mn0 = fminf(mn0, __shfl_xor_sync(0xffffffffu, mn0, off));
    if (lane == 0) sh_red[warp] = mn0;
    __syncthreads();                          // publishes sh_s2 + sh_red

    float s2b = sh_red[0];
    #pragma unroll
    for (int w = 1; w < NWARPS; ++w) s2b = fminf(s2b, sh_red[w]);

    const float m    = __fsqrt_rn(s2b);       // exact min chord
    const float cth  = m + DELTA_C;
    const float s2th = cth * cth;

    // ---- pass 2: float4 smem replay; branch-skipped rare body ----
    float ssum = 0.0f;
    const float4* __restrict__ s2v = (const float4*)sh_s2;
    for (int qb = 0; qb < n4; qb += NTHREADS) {
        const int q = qb + tid;
        float4 v = (q < n4) ? s2v[q] : make_float4(1e30f, 1e30f, 1e30f, 1e30f);
        bool h0 = v.x <= s2th, h1 = v.y <= s2th, h2 = v.z <= s2th, h3 = v.w <= s2th;
        if (__any_sync(0xffffffffu, h0 | h1 | h2 | h3)) {
            if (h0) ssum += exp2f(K0_CONST * (__fsqrt_rn(v.x) - m));
            if (h1) ssum += exp2f(K0_CONST * (__fsqrt_rn(v.y) - m));
            if (h2) ssum += exp2f(K0_CONST * (__fsqrt_rn(v.z) - m));
            if (h3) ssum += exp2f(K0_CONST * (__fsqrt_rn(v.w) - m));
        }
    }
    #pragma unroll
    for (int off = 16; off > 0; off >>= 1)
        ssum += __shfl_xor_sync(0xffffffffu, ssum, off);
    __syncthreads();                          // sh_red reuse
    if (lane == 0) sh_red[warp] = ssum;
    __syncthreads();

    if (tid == 0) {
        float S = sh_red[0];
        #pragma unroll
        for (int w = 1; w < NWARPS; ++w) S += sh_red[w];
        float soft = 0.0f, val = 0.0f;
        if (count > 0) {
            float d_min = (2.0f * EARTH_R) * asinf(fminf(0.5f * m, 1.0f));
            soft = d_min - 0.25f * logf(S);
            val  = 1.0f;
        }
        // L2 atomics (bypass L1 — no staleness), ticketed finalization
        atomicAdd(&g_sum_soft, soft);
        atomicAdd(&g_sum_valid, val);
        __threadfence();
        int t = atomicAdd(&g_ticket, 1);
        if (t == B_ROWS - 1) {
            float S0 = atomicAdd(&g_sum_soft, 0.0f);   // atomic read (L2)
            float V0 = atomicAdd(&g_sum_valid, 0.0f);
            out[0] = S0 / fmaxf(V0, 1.0f);
        }
    }
}

extern "C" void kernel_launch(void* const* d_in, const int* in_sizes, int n_in,
                              void* d_out, int out_size) {
    // Identify inputs by element count (all four are distinct).
    const float*     preds      = 0;   // 16384
    const float*     bin_coords = 0;   // 1024000
    const long long* x_vals     = 0;   // 24576
    const long long* bin_counts = 0;   // 125
    for (int i = 0; i < n_in; ++i) {
        switch (in_sizes[i]) {
            case 16384:   preds      = (const float*)d_in[i];     break;
            case 1024000: bin_coords = (const float*)d_in[i];     break;
            case 24576:   x_vals     = (const long long*)d_in[i]; break;
            case 125:     bin_counts = (const long long*)d_in[i]; break;
        }
    }
    float* out = (float*)d_out;

    const int prep_threads = NTOT / 4 + B_ROWS;
    prep_kernel<<<(prep_threads + 255) / 256, 256>>>(
        (const float4*)bin_coords, preds, x_vals, bin_counts);
    softbin_main_kernel<<<B_ROWS, NTHREADS>>>(out);
}

// round 17
// speedup vs baseline: 1.1110x; 1.1110x over previous
#include <cuda_runtime.h>

#define B_ROWS   8192
#define NBINS    125
#define M_CAND   4096
#define NTOT     (NBINS * M_CAND)
#define NTHREADS 128
#define NWARPS   4
#define EARTH_R  3958.8f
#define DEG2RAD  0.017453292519943295f
#define LOG2E    1.4426950408889634f
#define K0_CONST (-4.0f * EARTH_R * LOG2E)   /* chord-space logit slope, log2 */

// Static scratch (no allocations allowed)
__device__ float4 g_xyz[NTOT];     // candidate unit vectors (x,y,z,0)
__device__ float4 g_rowv[B_ROWS];  // row unit vectors
__device__ int2   g_meta[B_ROWS];  // (base index, count) per row
__device__ float  g_sum_soft;
__device__ float  g_sum_valid;
__device__ int    g_ticket;

// ---------------------------------------------------------------------------
// Kernel 1 (merged prep): candidates -> unit vectors (2 per thread, float4
// load); rows -> unit vector + (base, count) meta; reset accumulators.
// ---------------------------------------------------------------------------
__global__ __launch_bounds__(256)
void prep_kernel(const float4* __restrict__ bin_coords4,
                 const float* __restrict__ preds,
                 const long long* __restrict__ x_vals,
                 const long long* __restrict__ bin_counts) {
    int i = blockIdx.x * 256 + threadIdx.x;
    if (i == 0) { g_ticket = 0; g_sum_soft = 0.0f; g_sum_valid = 0.0f; }
    if (i < NTOT / 2) {
        float4 cc = __ldg(&bin_coords4[i]);   // two (lon, lat) pairs
        float slat0, clat0, slon0, clon0;
        float slat1, clat1, slon1, clon1;
        __sincosf(cc.y * DEG2RAD, &slat0, &clat0);
        __sincosf(cc.x * DEG2RAD, &slon0, &clon0);
        __sincosf(cc.w * DEG2RAD, &slat1, &clat1);
        __sincosf(cc.z * DEG2RAD, &slon1, &clon1);
        g_xyz[2 * i]     = make_float4(clat0 * clon0, clat0 * slon0, slat0, 0.0f);
        g_xyz[2 * i + 1] = make_float4(clat1 * clon1, clat1 * slon1, slat1, 0.0f);
    } else if (i < NTOT / 2 + B_ROWS) {
        int b = i - NTOT / 2;
        long long bin_id = x_vals[b * 3 + 0] * 25 + x_vals[b * 3 + 1] * 5 + x_vals[b * 3 + 2];
        if (bin_id < 0) bin_id = 0;
        if (bin_id >= NBINS) bin_id = NBINS - 1;
        int count = (int)bin_counts[bin_id];
        if (count < 0) count = 0;
        if (count > M_CAND) count = M_CAND;
        float lon = preds[b * 2 + 0] * DEG2RAD;
        float lat = preds[b * 2 + 1] * DEG2RAD;
        float slat, clat, slon, clon;
        sincosf(lat, &slat, &clat);           // libm accuracy once per row
        sincosf(lon, &slon, &clon);
        g_rowv[b] = make_float4(clat * clon, clat * slon, slat, 0.0f);
        g_meta[b] = make_int2((int)bin_id * M_CAND, count);
    }
}

// ---------------------------------------------------------------------------
// Kernel 2: row-centric single pass, online chord-space logsumexp with four
// independent accumulators; fused L2-atomic tail reduction (ticketed).
// ---------------------------------------------------------------------------
__global__ __launch_bounds__(NTHREADS)
void softbin_main_kernel(float* __restrict__ out) {
    __shared__ float sh_m[NWARPS];
    __shared__ float sh_s[NWARPS];

    const int b    = blockIdx.x;
    const int tid  = threadIdx.x;
    const int warp = tid >> 5;
    const int lane = tid & 31;

    const int2  mt  = g_meta[b];
    const int base  = mt.x;
    const int count = mt.y;
    const float4 rv = g_rowv[b];              // broadcast LDG.128
    const float px = rv.x, py = rv.y, pz = rv.z;

    const float4* __restrict__ cand = g_xyz + base;

    // Four independent online states
    float m0 = 1.0e30f, s0 = 0.0f;
    float m1 = 1.0e30f, s1 = 0.0f;
    float m2 = 1.0e30f, s2a = 0.0f;
    float m3 = 1.0e30f, s3 = 0.0f;

    int j = tid;
    for (; j + 3 * NTHREADS < count; j += 4 * NTHREADS) {
        float4 c0 = __ldg(&cand[j]);
        float4 c1 = __ldg(&cand[j + NTHREADS]);
        float4 c2 = __ldg(&cand[j + 2 * NTHREADS]);
        float4 c3 = __ldg(&cand[j + 3 * NTHREADS]);
        {
            float dx = px - c0.x, dy = py - c0.y, dz = pz - c0.z;
            float cc = __fsqrt_rn(fmaf(dx, dx, fmaf(dy, dy, dz * dz)));
            float e  = exp2f(K0_CONST * fabsf(cc - m0));
            s0 = (cc < m0) ? fmaf(s0, e, 1.0f) : (s0 + e);
            m0 = fminf(m0, cc);
        }
        {
            float dx = px - c1.x, dy = py - c1.y, dz = pz - c1.z;
            float cc = __fsqrt_rn(fmaf(dx, dx, fmaf(dy, dy, dz * dz)));
            float e  = exp2f(K0_CONST * fabsf(cc - m1));
            s1 = (cc < m1) ? fmaf(s1, e, 1.0f) : (s1 + e);
            m1 = fminf(m1, cc);
        }
        {
            float dx = px - c2.x, dy = py - c2.y, dz = pz - c2.z;
            float cc = __fsqrt_rn(fmaf(dx, dx, fmaf(dy, dy, dz * dz)));
            float e  = exp2f(K0_CONST * fabsf(cc - m2));
            s2a = (cc < m2) ? fmaf(s2a, e, 1.0f) : (s2a + e);
            m2 = fminf(m2, cc);
        }
        {
            float dx = px - c3.x, dy = py - c3.y, dz = pz - c3.z;
            float cc = __fsqrt_rn(fmaf(dx, dx, fmaf(dy, dy, dz * dz)));
            float e  = exp2f(K0_CONST * fabsf(cc - m3));
            s3 = (cc < m3) ? fmaf(s3, e, 1.0f) : (s3 + e);
            m3 = fminf(m3, cc);
        }
    }
    for (; j < count; j += NTHREADS) {
        float4 c0 = __ldg(&cand[j]);
        float dx = px - c0.x, dy = py - c0.y, dz = pz - c0.z;
        float cc = __fsqrt_rn(fmaf(dx, dx, fmaf(dy, dy, dz * dz)));
        float e  = exp2f(K0_CONST * fabsf(cc - m0));
        s0 = (cc < m0) ? fmaf(s0, e, 1.0f) : (s0 + e);
        m0 = fminf(m0, cc);
    }

    // Merge accumulators pairwise (exact logsumexp algebra)
    {
        float mn = fminf(m0, m1);
        s0 = s0 * exp2f(K0_CONST * (m0 - mn)) + s1 * exp2f(K0_CONST * (m1 - mn));
        m0 = mn;
    }
    {
        float mn = fminf(m2, m3);
        s2a = s2a * exp2f(K0_CONST * (m2 - mn)) + s3 * exp2f(K0_CONST * (m3 - mn));
        m2 = mn;
    }
    {
        float mn = fminf(m0, m2);
        s0 = s0 * exp2f(K0_CONST * (m0 - mn)) + s2a * exp2f(K0_CONST * (m2 - mn));
        m0 = mn;
    }

    // Warp-level (m, s) combine
    #pragma unroll
    for (int off = 16; off > 0; off >>= 1) {
        float mo = __shfl_xor_sync(0xffffffffu, m0, off);
        float so = __shfl_xor_sync(0xffffffffu, s0, off);
        float mn = fminf(m0, mo);
        s0 = s0 * exp2f(K0_CONST * (m0 - mn))
           + so * exp2f(K0_CONST * (mo - mn));
        m0 = mn;
    }
    if (lane == 0) { sh_m[warp] = m0; sh_s[warp] = s0; }
    __syncthreads();

    if (tid == 0) {
        float M0 = sh_m[0], S0 = sh_s[0];
        #pragma unroll
        for (int w = 1; w < NWARPS; ++w) {
            float mo = sh_m[w], so = sh_s[w];
            float mn = fminf(M0, mo);
            S0 = S0 * exp2f(K0_CONST * (M0 - mn))
               + so * exp2f(K0_CONST * (mo - mn));
            M0 = mn;
        }
        float soft = 0.0f, val = 0.0f;
        if (count > 0) {
            float d_min = (2.0f * EARTH_R) * asinf(fminf(0.5f * M0, 1.0f));
            soft = d_min - 0.25f * logf(S0);
            val  = 1.0f;
        }
        // L2 atomics (bypass L1 — no staleness), ticketed finalization
        atomicAdd(&g_sum_soft, soft);
        atomicAdd(&g_sum_valid, val);
        __threadfence();
        int t = atomicAdd(&g_ticket, 1);
        if (t == B_ROWS - 1) {
            float S = atomicAdd(&g_sum_soft, 0.0f);    // atomic read (L2)
            float V = atomicAdd(&g_sum_valid, 0.0f);
            out[0] = S / fmaxf(V, 1.0f);
        }
    }
}

extern "C" void kernel_launch(void* const* d_in, const int* in_sizes, int n_in,
                              void* d_out, int out_size) {
    // Identify inputs by element count (all four are distinct).
    const float*     preds      = 0;   // 16384
    const float*     bin_coords = 0;   // 1024000
    const long long* x_vals     = 0;   // 24576
    const long long* bin_counts = 0;   // 125
    for (int i = 0; i < n_in; ++i) {
        switch (in_sizes[i]) {
            case 16384:   preds      = (const float*)d_in[i];     break;
            case 1024000: bin_coords = (const float*)d_in[i];     break;
            case 24576:   x_vals     = (const long long*)d_in[i]; break;
            case 125:     bin_counts = (const long long*)d_in[i]; break;
        }
    }
    float* out = (float*)d_out;

    const int prep_threads = NTOT / 2 + B_ROWS;
    prep_kernel<<<(prep_threads + 255) / 256, 256>>>(
        (const float4*)bin_coords, preds, x_vals, bin_counts);
    softbin_main_kernel<<<B_ROWS, NTHREADS>>>(out);
}